// round 10
// baseline (speedup 1.0000x reference)
#include <cuda_runtime.h>
#include <math.h>
#include <stdint.h>

// Problem constants (fixed by the dataset)
#define NN      4096
#define MM      2048
#define DVV     3
#define DCC     6
#define EE      (NN*DVV)      // 12288
#define BB      2048
#define NITER   5
#define THREADS 512
#define CN_T    (MM/THREADS)  // 4 CN tasks per thread
#define VN_T    (NN/THREADS)  // 8 VN tasks per thread

// SMEM: msg buf only (E floats) = 49152 B -> 3 CTAs/SM (144KB of 228KB)
#define SMEM_BYTES (EE*4)

// ---------------------------------------------------------------------------
// MUFU intrinsics
// ---------------------------------------------------------------------------
__device__ __forceinline__ float ex2a(float x){ float r; asm("ex2.approx.ftz.f32 %0, %1;" : "=f"(r) : "f"(x)); return r; }
__device__ __forceinline__ float lg2a(float x){ float r; asm("lg2.approx.ftz.f32 %0, %1;" : "=f"(r) : "f"(x)); return r; }

#define LOG2E_F 1.4426950408889634f
#define LN2_F   0.6931471805599453f
#define FMAX_F  27.631021115928547f   /* -ln(1e-12): emulates log(|t|+eps) floor */
#define MAGMAX  16.635532f            /* 2*atanh(float(1-1e-7)): emulates CLIP   */

// f(x) = -ln(tanh(x/2)), x >= 0. Self-inverse. Scalar, immediate-form FFMA
// (all constants are immediates -> minimal register pressure).
__device__ __forceinline__ float f_op(float ax)
{
    // regime A (ax >= 1): f = 2*atanh(u), u = e^{-ax}
    float u  = ex2a(-ax * LOG2E_F);
    float u2 = u * u;
    float qL = fmaf(u2, 0.22222222f, 0.28571429f);   // 2/9, 2/7
    qL       = fmaf(u2, qL, 0.4f);                   // 2/5
    qL       = fmaf(u2, qL, 0.66666667f);            // 2/3
    qL       = fmaf(u2, qL, 2.0f);
    float fL = u * qL;

    // regime B (ax < 1): f = ln2*(1 - lg2(ax)) + ax^2/12 - 7ax^4/1440 + 62ax^6/181440
    float l  = lg2a(ax);
    float y  = ax * ax;
    float pS = fmaf(y, 3.4171076e-4f, -4.8611111e-3f);
    pS       = fmaf(y, pS, 8.3333333e-2f);
    float fS = fmaf(y, pS, fmaf(l, -LN2_F, LN2_F));

    return (ax >= 1.0f) ? fL : fS;
}

// ---------------------------------------------------------------------------
// Persistent scratch (static globals: no runtime allocation)
// ---------------------------------------------------------------------------
__device__ int   g_cnt[MM];
__device__ int   g_tmp[EE];        // g_tmp[m*6+slot] = edge id (atomic order)
__device__ uint4 g_cnp[MM * 3];    // per CN: [8 x u16 byte-offsets][6 x f32 weights]

// ---------------------------------------------------------------------------
// Prep kernels (deterministic after the sort)
// ---------------------------------------------------------------------------
__global__ void prep_zero()
{
    int i = blockIdx.x * blockDim.x + threadIdx.x;
    if (i < MM) g_cnt[i] = 0;
}

__global__ void prep_fill(const int* __restrict__ cn_idx)
{
    int e = blockIdx.x * blockDim.x + threadIdx.x;
    if (e < EE) {
        int m = cn_idx[e];
        int p = atomicAdd(&g_cnt[m], 1);
        g_tmp[m * DCC + p] = e;
    }
}

__global__ void prep_pack(const float* __restrict__ w)
{
    int m = blockIdx.x * blockDim.x + threadIdx.x;
    if (m >= MM) return;
    int a[DCC];
#pragma unroll
    for (int j = 0; j < DCC; j++) a[j] = g_tmp[m * DCC + j];
    // sort ascending -> deterministic edge order matching jax scatter-add
#pragma unroll
    for (int i = 0; i < DCC - 1; i++)
#pragma unroll
        for (int j = 0; j < DCC - 1 - i; j++)
            if (a[j] > a[j + 1]) { int t = a[j]; a[j] = a[j + 1]; a[j + 1] = t; }

    uint4 iw;   // 8 x u16 byte offsets (e*4 < 49152 fits u16), slots 6,7 = 0
    iw.x = (unsigned)(a[0] * 4) | ((unsigned)(a[1] * 4) << 16);
    iw.y = (unsigned)(a[2] * 4) | ((unsigned)(a[3] * 4) << 16);
    iw.z = (unsigned)(a[4] * 4) | ((unsigned)(a[5] * 4) << 16);
    iw.w = 0;
    g_cnp[m * 3 + 0] = iw;

    uint4 w0, w1;
    w0.x = __float_as_uint(w[a[0]]); w0.y = __float_as_uint(w[a[1]]);
    w0.z = __float_as_uint(w[a[2]]); w0.w = __float_as_uint(w[a[3]]);
    w1.x = __float_as_uint(w[a[4]]); w1.y = __float_as_uint(w[a[5]]);
    w1.z = 0u; w1.w = 0u;
    g_cnp[m * 3 + 1] = w0;
    g_cnp[m * 3 + 2] = w1;
}

// ---------------------------------------------------------------------------
// Main BP kernel: one CTA per batch row, msg buf in SMEM (48KB), llr in
// registers, 3 CTAs/SM (48 warps) for latency hiding.
// ---------------------------------------------------------------------------
__global__ __launch_bounds__(THREADS, 3)
void bp_kernel(const float* __restrict__ noise_r,
               float* __restrict__ out)
{
    extern __shared__ unsigned char smem_raw[];
    float* buf = reinterpret_cast<float*>(smem_raw);   // E floats

    const int row = blockIdx.x;
    const int tid = threadIdx.x;
    const float* nr = noise_r + (size_t)row * NN;

    const float NO_F = 0.3981071705534972f;   // 10^-0.4
    const float NSTD = 0.44615420f;           // sqrtf(no/2) in f32

    // llr lives in registers: one scalar per owned VN (8 regs)
    float llr_r[VN_T];

    // ---- init: llr (regs) + msg_vn (smem) ----
#pragma unroll
    for (int k = 0; k < VN_T; ++k) {
        const int v = tid + k * THREADS;
        float l = (4.0f * (1.0f + NSTD * nr[v])) / NO_F;
        llr_r[k] = l;
        buf[3 * v + 0] = l;
        buf[3 * v + 1] = l;
        buf[3 * v + 2] = l;
    }
    __syncthreads();

    for (int it = 0; it < NITER; ++it) {
        // ---- check-node pass (tanh/log fused, registers only) ----
#pragma unroll 1
        for (int k = 0; k < CN_T; ++k) {
            const int m = tid + k * THREADS;
            const uint4 iw = __ldg(&g_cnp[m * 3 + 0]);
            const uint4 wa = __ldg(&g_cnp[m * 3 + 1]);
            const uint4 wb = __ldg(&g_cnp[m * 3 + 2]);

            unsigned off[6];
            off[0] = iw.x & 0xFFFFu;  off[1] = iw.x >> 16;
            off[2] = iw.y & 0xFFFFu;  off[3] = iw.y >> 16;
            off[4] = iw.z & 0xFFFFu;  off[5] = iw.z >> 16;
            float wgt[6];
            wgt[0] = __uint_as_float(wa.x); wgt[1] = __uint_as_float(wa.y);
            wgt[2] = __uint_as_float(wa.z); wgt[3] = __uint_as_float(wa.w);
            wgt[4] = __uint_as_float(wb.x); wgt[5] = __uint_as_float(wb.y);

            float    fv[6];
            unsigned sgn = 0u;
            float    S   = 0.0f;
#pragma unroll
            for (int j = 0; j < 6; ++j) {
                float x  = *reinterpret_cast<const float*>(smem_raw + off[j]) * wgt[j];
                sgn     |= (__float_as_uint(x) >> 31) << j;
                float fj = fminf(f_op(fabsf(x)), FMAX_F);   // = -log(|tanh(x/2)|+eps)
                fv[j]    = fj;
                S       += fj;           // ascending edge order (matches ref)
            }
            const unsigned par = __popc(sgn) & 1u;
#pragma unroll
            for (int j = 0; j < 6; ++j) {
                float el  = fmaxf(S - fv[j], 0.0f);
                float mag = fminf(f_op(el), MAGMAX);        // = 2*atanh(clip(exp(-el)))
                unsigned bits = __float_as_uint(mag) | ((par ^ ((sgn >> j) & 1u)) << 31);
                *reinterpret_cast<float*>(smem_raw + off[j]) = __uint_as_float(bits);
            }
        }
        __syncthreads();

        // ---- variable-node pass: the 3 edges of VN v are contiguous ----
        const bool last = (it == NITER - 1);
#pragma unroll
        for (int k = 0; k < VN_T; ++k) {
            const int v = tid + k * THREADS;
            float m0 = buf[3 * v + 0];
            float m1 = buf[3 * v + 1];
            float m2 = buf[3 * v + 2];
            float lt = llr_r[k] + ((m0 + m1) + m2);   // ascending edge order
            if (last) {
                out[(size_t)row * NN + v] = lt;
            } else {
                buf[3 * v + 0] = lt - m0;
                buf[3 * v + 1] = lt - m1;
                buf[3 * v + 2] = lt - m2;
            }
        }
        __syncthreads();
    }
}

// ---------------------------------------------------------------------------
// Launch
// ---------------------------------------------------------------------------
extern "C" void kernel_launch(void* const* d_in, const int* in_sizes, int n_in,
                              void* d_out, int out_size)
{
    const float* noise_r = (const float*)d_in[0];
    // d_in[1] = noise_i (unused by the reference)
    const float* weights = (const float*)d_in[2];
    // d_in[3] = vn_idx (structural: e/3)
    const int*   cn_idx  = (const int*)d_in[4];
    float* out = (float*)d_out;

    (void)in_sizes; (void)n_in; (void)out_size;

    cudaFuncSetAttribute(bp_kernel, cudaFuncAttributeMaxDynamicSharedMemorySize, SMEM_BYTES);

    prep_zero<<<(MM + 255) / 256, 256>>>();
    prep_fill<<<(EE + 255) / 256, 256>>>(cn_idx);
    prep_pack<<<(MM + 255) / 256, 256>>>(weights);

    bp_kernel<<<BB, THREADS, SMEM_BYTES>>>(noise_r, out);
}

// round 11
// speedup vs baseline: 1.0642x; 1.0642x over previous
#include <cuda_runtime.h>
#include <math.h>
#include <stdint.h>

// Problem constants (fixed by the dataset)
#define NN      4096
#define MM      2048
#define DVV     3
#define DCC     6
#define EE      (NN*DVV)      // 12288
#define BB      2048
#define NITER   5
#define THREADS 512
#define CN_T    (MM/THREADS)  // 4 CN tasks per thread (each covers 2 rows)
#define VN_T    (NN/THREADS)  // 8 VN tasks per thread

// SMEM: SoA msg planes: 3 planes of NN packed f32x2 = 98304 B -> 2 CTAs/SM
#define SMEM_BYTES (EE*8)

typedef unsigned long long ull;

// ---------------------------------------------------------------------------
// f32x2 + MUFU helpers
// ---------------------------------------------------------------------------
__device__ __forceinline__ float ex2a(float x){ float r; asm("ex2.approx.ftz.f32 %0, %1;" : "=f"(r) : "f"(x)); return r; }
__device__ __forceinline__ float lg2a(float x){ float r; asm("lg2.approx.ftz.f32 %0, %1;" : "=f"(r) : "f"(x)); return r; }

__device__ __forceinline__ ull  pk2(float a, float b){ ull r; asm("mov.b64 %0, {%1, %2};" : "=l"(r) : "f"(a), "f"(b)); return r; }
__device__ __forceinline__ void upk2(ull x, float& a, float& b){ asm("mov.b64 {%0, %1}, %2;" : "=f"(a), "=f"(b) : "l"(x)); }
__device__ __forceinline__ ull  fma2(ull a, ull b, ull c){ ull r; asm("fma.rn.f32x2 %0, %1, %2, %3;" : "=l"(r) : "l"(a), "l"(b), "l"(c)); return r; }
__device__ __forceinline__ ull  mul2(ull a, ull b){ ull r; asm("mul.rn.f32x2 %0, %1, %2;" : "=l"(r) : "l"(a), "l"(b)); return r; }
__device__ __forceinline__ ull  add2(ull a, ull b){ ull r; asm("add.rn.f32x2 %0, %1, %2;" : "=l"(r) : "l"(a), "l"(b)); return r; }

#define LOG2E_F 1.4426950408889634f
#define LN2_F   0.6931471805599453f
#define FMAX_F  27.631021115928547f   /* -ln(1e-12): emulates log(|t|+eps) floor */
#define MAGMAX  16.635532f            /* 2*atanh(float(1-1e-7)): emulates CLIP   */

// f(x) = -ln(tanh(x/2)) on a pair of nonneg inputs. Self-inverse.
// 4 MUFU + packed f32x2 chains.
__device__ __forceinline__ void f_op2(float al, float ah, float& rl, float& rh)
{
    const ull C27 = pk2(0.2857143f,  0.2857143f);   // 2/7
    const ull C25 = pk2(0.4f,        0.4f);         // 2/5
    const ull C23 = pk2(0.66666667f, 0.66666667f);  // 2/3
    const ull C2  = pk2(2.0f,        2.0f);
    const ull K6  = pk2(3.4171076e-4f,  3.4171076e-4f);
    const ull K4  = pk2(-4.8611111e-3f, -4.8611111e-3f);
    const ull K2  = pk2(8.3333333e-2f,  8.3333333e-2f);
    const ull NL2 = pk2(-LN2_F, -LN2_F);
    const ull PL2 = pk2( LN2_F,  LN2_F);

    // regime A (a >= 1): f = 2*atanh(u), u = e^{-a}
    float ul = ex2a(-al * LOG2E_F);
    float uh = ex2a(-ah * LOG2E_F);
    ull u  = pk2(ul, uh);
    ull us = mul2(u, u);
    ull q  = fma2(us, C27, C25);
    q      = fma2(us, q,   C23);
    q      = fma2(us, q,   C2);
    ull fL = mul2(u, q);

    // regime B (a < 1): f = ln2*(1 - lg2(a)) + a^2/12 - 7a^4/1440 + 62a^6/181440
    float ll = lg2a(al);
    float lh = lg2a(ah);
    ull a2   = pk2(al, ah);
    ull y    = mul2(a2, a2);
    ull p    = fma2(y, K6, K4);
    p        = fma2(y, p,  K2);
    ull base = fma2(pk2(ll, lh), NL2, PL2);
    ull fS   = fma2(y, p, base);

    float fLl, fLh, fSl, fSh;
    upk2(fL, fLl, fLh);
    upk2(fS, fSl, fSh);
    rl = (al >= 1.0f) ? fLl : fSl;
    rh = (ah >= 1.0f) ? fLh : fSh;
}

// ---------------------------------------------------------------------------
// Persistent scratch (static globals: no runtime allocation)
// ---------------------------------------------------------------------------
__device__ int   g_cnt[MM];
__device__ int   g_tmp[EE];        // g_tmp[m*6+slot] = edge id (atomic order)
__device__ uint4 g_cnp[MM * 3];    // per CN: 6 x u32 SoA byte-offsets, 6 x f32 weights

// ---------------------------------------------------------------------------
// Prep kernels (deterministic after the sort)
// ---------------------------------------------------------------------------
__global__ void prep_zero()
{
    int i = blockIdx.x * blockDim.x + threadIdx.x;
    if (i < MM) g_cnt[i] = 0;
}

__global__ void prep_fill(const int* __restrict__ cn_idx)
{
    int e = blockIdx.x * blockDim.x + threadIdx.x;
    if (e < EE) {
        int m = cn_idx[e];
        int p = atomicAdd(&g_cnt[m], 1);
        g_tmp[m * DCC + p] = e;
    }
}

// SoA byte offset of edge e: plane (e%3), index (e/3), 8 bytes per entry
__device__ __forceinline__ unsigned soa_off(int e)
{
    return (unsigned)(((e % DVV) * NN + (e / DVV)) * 8);
}

__global__ void prep_pack(const float* __restrict__ w)
{
    int m = blockIdx.x * blockDim.x + threadIdx.x;
    if (m >= MM) return;
    int a[DCC];
#pragma unroll
    for (int j = 0; j < DCC; j++) a[j] = g_tmp[m * DCC + j];
    // sort ascending -> deterministic edge order matching jax scatter-add
#pragma unroll
    for (int i = 0; i < DCC - 1; i++)
#pragma unroll
        for (int j = 0; j < DCC - 1 - i; j++)
            if (a[j] > a[j + 1]) { int t = a[j]; a[j] = a[j + 1]; a[j + 1] = t; }

    uint4 p0, p1, p2;
    p0.x = soa_off(a[0]); p0.y = soa_off(a[1]);
    p0.z = soa_off(a[2]); p0.w = soa_off(a[3]);
    p1.x = soa_off(a[4]); p1.y = soa_off(a[5]);
    p1.z = __float_as_uint(w[a[0]]); p1.w = __float_as_uint(w[a[1]]);
    p2.x = __float_as_uint(w[a[2]]); p2.y = __float_as_uint(w[a[3]]);
    p2.z = __float_as_uint(w[a[4]]); p2.w = __float_as_uint(w[a[5]]);
    g_cnp[m * 3 + 0] = p0;
    g_cnp[m * 3 + 1] = p1;
    g_cnp[m * 3 + 2] = p2;
}

// ---------------------------------------------------------------------------
// Main BP kernel: one CTA per 2 batch rows, SoA msg planes (packed f32x2) in
// SMEM, packed math, llr pairs in registers, full unroll. 2 CTAs/SM.
// ---------------------------------------------------------------------------
__global__ __launch_bounds__(THREADS, 2)
void bp_kernel(const float* __restrict__ noise_r,
               float* __restrict__ out)
{
    extern __shared__ ull smem8[];
    ull* P0 = smem8;            // plane 0: NN packed pairs
    ull* P1 = smem8 + NN;       // plane 1
    ull* P2 = smem8 + 2 * NN;   // plane 2

    const int tid  = threadIdx.x;
    const int rowA = blockIdx.x * 2;
    const float* nra = noise_r + (size_t)rowA * NN;
    const float* nrb = nra + NN;

    const float NO_F = 0.3981071705534972f;   // 10^-0.4
    const float NSTD = 0.44615420f;           // sqrtf(no/2) in f32
    const ull   NEG1 = pk2(-1.0f, -1.0f);

    // llr lives in registers: one packed pair per owned VN
    ull llr_r[VN_T];

    // ---- init: llr (regs) + msg planes (coalesced) ----
#pragma unroll
    for (int k = 0; k < VN_T; ++k) {
        const int v = tid + k * THREADS;
        float la = (4.0f * (1.0f + NSTD * nra[v])) / NO_F;
        float lb = (4.0f * (1.0f + NSTD * nrb[v])) / NO_F;
        ull l2 = pk2(la, lb);
        llr_r[k] = l2;
        P0[v] = l2;
        P1[v] = l2;
        P2[v] = l2;
    }
    __syncthreads();

    for (int it = 0; it < NITER; ++it) {
        // ---- check-node pass (tanh/log fused, both rows, packed math) ----
#pragma unroll
        for (int k = 0; k < CN_T; ++k) {
            const int m = tid + k * THREADS;
            const uint4 p0 = __ldg(&g_cnp[m * 3 + 0]);
            const uint4 p1 = __ldg(&g_cnp[m * 3 + 1]);
            const uint4 p2 = __ldg(&g_cnp[m * 3 + 2]);

            unsigned off[6] = { p0.x, p0.y, p0.z, p0.w, p1.x, p1.y };
            float    wgt[6] = { __uint_as_float(p1.z), __uint_as_float(p1.w),
                                __uint_as_float(p2.x), __uint_as_float(p2.y),
                                __uint_as_float(p2.z), __uint_as_float(p2.w) };

            ull      fv[6];
            unsigned sl = 0u, sh = 0u;   // per-row sign bitmasks (bit j)
            ull      S  = 0ull;          // packed {0.f, 0.f}
#pragma unroll
            for (int j = 0; j < 6; ++j) {
                ull mm = *reinterpret_cast<const ull*>(
                             reinterpret_cast<const char*>(smem8) + off[j]);
                float xl, xh; upk2(mm, xl, xh);
                xl *= wgt[j];
                xh *= wgt[j];
                sl |= (__float_as_uint(xl) >> 31) << j;
                sh |= (__float_as_uint(xh) >> 31) << j;
                float fl, fh;
                f_op2(fabsf(xl), fabsf(xh), fl, fh);
                fl = fminf(fl, FMAX_F);
                fh = fminf(fh, FMAX_F);
                fv[j] = pk2(fl, fh);
                S = add2(S, fv[j]);      // ascending edge order (matches ref)
            }
            const unsigned pl = __popc(sl) & 1u;
            const unsigned ph = __popc(sh) & 1u;
#pragma unroll
            for (int j = 0; j < 6; ++j) {
                ull e2 = fma2(fv[j], NEG1, S);      // S - fv[j]
                float el, eh; upk2(e2, el, eh);
                el = fmaxf(el, 0.0f);
                eh = fmaxf(eh, 0.0f);
                float gl, gh;
                f_op2(el, eh, gl, gh);              // = 2*atanh(clip(exp(-el)))
                gl = fminf(gl, MAGMAX);
                gh = fminf(gh, MAGMAX);
                unsigned rl = __float_as_uint(gl) | ((pl ^ ((sl >> j) & 1u)) << 31);
                unsigned rh = __float_as_uint(gh) | ((ph ^ ((sh >> j) & 1u)) << 31);
                *reinterpret_cast<ull*>(reinterpret_cast<char*>(smem8) + off[j]) =
                    pk2(__uint_as_float(rl), __uint_as_float(rh));
            }
        }
        __syncthreads();

        // ---- variable-node pass: coalesced SoA planes, llr from registers ----
        const bool last = (it == NITER - 1);
#pragma unroll
        for (int k = 0; k < VN_T; ++k) {
            const int v = tid + k * THREADS;
            ull m0 = P0[v];
            ull m1 = P1[v];
            ull m2 = P2[v];
            ull s  = add2(add2(m0, m1), m2);   // ascending edge order
            ull lt = add2(llr_r[k], s);
            if (last) {
                float a, b; upk2(lt, a, b);
                out[(size_t)rowA * NN + v]       = a;
                out[(size_t)(rowA + 1) * NN + v] = b;
            } else {
                P0[v] = fma2(m0, NEG1, lt);
                P1[v] = fma2(m1, NEG1, lt);
                P2[v] = fma2(m2, NEG1, lt);
            }
        }
        __syncthreads();
    }
}

// ---------------------------------------------------------------------------
// Launch
// ---------------------------------------------------------------------------
extern "C" void kernel_launch(void* const* d_in, const int* in_sizes, int n_in,
                              void* d_out, int out_size)
{
    const float* noise_r = (const float*)d_in[0];
    // d_in[1] = noise_i (unused by the reference)
    const float* weights = (const float*)d_in[2];
    // d_in[3] = vn_idx (structural: e/3)
    const int*   cn_idx  = (const int*)d_in[4];
    float* out = (float*)d_out;

    (void)in_sizes; (void)n_in; (void)out_size;

    cudaFuncSetAttribute(bp_kernel, cudaFuncAttributeMaxDynamicSharedMemorySize, SMEM_BYTES);

    prep_zero<<<(MM + 255) / 256, 256>>>();
    prep_fill<<<(EE + 255) / 256, 256>>>(cn_idx);
    prep_pack<<<(MM + 255) / 256, 256>>>(weights);

    bp_kernel<<<BB / 2, THREADS, SMEM_BYTES>>>(noise_r, out);
}

// round 12
// speedup vs baseline: 1.3561x; 1.2742x over previous
#include <cuda_runtime.h>
#include <math.h>
#include <stdint.h>

// Problem constants (fixed by the dataset)
#define NN      4096
#define MM      2048
#define DVV     3
#define DCC     6
#define EE      (NN*DVV)      // 12288
#define BB      2048
#define NITER   5
#define THREADS 512
#define CN_T    (MM/THREADS)  // 4 CN tasks per thread (each covers 2 rows)
#define VN_T    (NN/THREADS)  // 8 VN tasks per thread

// SMEM: SoA msg planes: 3 planes of NN packed f32x2 = 98304 B -> 2 CTAs/SM
#define SMEM_BYTES (EE*8)

typedef unsigned long long ull;

// ---------------------------------------------------------------------------
// MUFU + pack helpers
// ---------------------------------------------------------------------------
__device__ __forceinline__ float ex2a(float x){ float r; asm("ex2.approx.ftz.f32 %0, %1;" : "=f"(r) : "f"(x)); return r; }
__device__ __forceinline__ float lg2a(float x){ float r; asm("lg2.approx.ftz.f32 %0, %1;" : "=f"(r) : "f"(x)); return r; }
__device__ __forceinline__ float rcpa(float x){ float r; asm("rcp.approx.ftz.f32 %0, %1;" : "=f"(r) : "f"(x)); return r; }
__device__ __forceinline__ ull  pk2(float a, float b){ ull r; asm("mov.b64 %0, {%1, %2};" : "=l"(r) : "f"(a), "f"(b)); return r; }
__device__ __forceinline__ void upk2(ull x, float& a, float& b){ asm("mov.b64 {%0, %1}, %2;" : "=f"(a), "=f"(b) : "l"(x)); }
__device__ __forceinline__ ull  fma2(ull a, ull b, ull c){ ull r; asm("fma.rn.f32x2 %0, %1, %2, %3;" : "=l"(r) : "l"(a), "l"(b), "l"(c)); return r; }
__device__ __forceinline__ ull  add2(ull a, ull b){ ull r; asm("add.rn.f32x2 %0, %1, %2;" : "=l"(r) : "l"(a), "l"(b)); return r; }

#define LOG2E_F 1.4426950408889634f
#define LN2_F   0.6931471805599453f
#define MAGMAX  16.635532f            /* 2*atanh(float(1-1e-7)): emulates CLIP    */
#define UMAX_F  0.99999988f           /* 1-2^-23: keeps 1-u and products nonzero  */

// ---------------------------------------------------------------------------
// Persistent scratch (static globals: no runtime allocation)
// ---------------------------------------------------------------------------
__device__ int   g_cnt[MM];
__device__ int   g_tmp[EE];        // g_tmp[m*6+slot] = edge id (atomic order)
__device__ uint4 g_cnp[MM * 3];    // per CN: 6 x u32 SoA byte-offsets, 6 x f32 weights

// ---------------------------------------------------------------------------
// Prep kernels (deterministic after the sort)
// ---------------------------------------------------------------------------
__global__ void prep_zero()
{
    int i = blockIdx.x * blockDim.x + threadIdx.x;
    if (i < MM) g_cnt[i] = 0;
}

__global__ void prep_fill(const int* __restrict__ cn_idx)
{
    int e = blockIdx.x * blockDim.x + threadIdx.x;
    if (e < EE) {
        int m = cn_idx[e];
        int p = atomicAdd(&g_cnt[m], 1);
        g_tmp[m * DCC + p] = e;
    }
}

// SoA byte offset of edge e: plane (e%3), index (e/3), 8 bytes per entry
__device__ __forceinline__ unsigned soa_off(int e)
{
    return (unsigned)(((e % DVV) * NN + (e / DVV)) * 8);
}

__global__ void prep_pack(const float* __restrict__ w)
{
    int m = blockIdx.x * blockDim.x + threadIdx.x;
    if (m >= MM) return;
    int a[DCC];
#pragma unroll
    for (int j = 0; j < DCC; j++) a[j] = g_tmp[m * DCC + j];
    // sort ascending -> deterministic edge order matching jax scatter-add
#pragma unroll
    for (int i = 0; i < DCC - 1; i++)
#pragma unroll
        for (int j = 0; j < DCC - 1 - i; j++)
            if (a[j] > a[j + 1]) { int t = a[j]; a[j] = a[j + 1]; a[j + 1] = t; }

    uint4 p0, p1, p2;
    p0.x = soa_off(a[0]); p0.y = soa_off(a[1]);
    p0.z = soa_off(a[2]); p0.w = soa_off(a[3]);
    p1.x = soa_off(a[4]); p1.y = soa_off(a[5]);
    p1.z = __float_as_uint(w[a[0]]); p1.w = __float_as_uint(w[a[1]]);
    p2.x = __float_as_uint(w[a[2]]); p2.y = __float_as_uint(w[a[3]]);
    p2.z = __float_as_uint(w[a[4]]); p2.w = __float_as_uint(w[a[5]]);
    g_cnp[m * 3 + 0] = p0;
    g_cnp[m * 3 + 1] = p1;
    g_cnp[m * 3 + 2] = p2;
}

// ---------------------------------------------------------------------------
// Main BP kernel: one CTA per 2 batch rows, SoA msg planes (packed f32x2) in
// SMEM, product-domain CN update (3.2 MUFU/edge), llr pairs in registers.
// 2 CTAs/SM.
// ---------------------------------------------------------------------------
__global__ __launch_bounds__(THREADS, 2)
void bp_kernel(const float* __restrict__ noise_r,
               float* __restrict__ out)
{
    extern __shared__ ull smem8[];
    ull* P0 = smem8;            // plane 0: NN packed pairs
    ull* P1 = smem8 + NN;       // plane 1
    ull* P2 = smem8 + 2 * NN;   // plane 2

    const int tid  = threadIdx.x;
    const int rowA = blockIdx.x * 2;
    const float* nra = noise_r + (size_t)rowA * NN;
    const float* nrb = nra + NN;

    const float NO_F = 0.3981071705534972f;   // 10^-0.4
    const float NSTD = 0.44615420f;           // sqrtf(no/2) in f32
    const ull   NEG1 = pk2(-1.0f, -1.0f);

    // llr lives in registers: one packed pair per owned VN
    ull llr_r[VN_T];

    // ---- init: llr (regs) + msg planes (coalesced) ----
#pragma unroll
    for (int k = 0; k < VN_T; ++k) {
        const int v = tid + k * THREADS;
        float la = (4.0f * (1.0f + NSTD * nra[v])) / NO_F;
        float lb = (4.0f * (1.0f + NSTD * nrb[v])) / NO_F;
        ull l2 = pk2(la, lb);
        llr_r[k] = l2;
        P0[v] = l2;
        P1[v] = l2;
        P2[v] = l2;
    }
    __syncthreads();

    for (int it = 0; it < NITER; ++it) {
        // ---- check-node pass: product-domain tanh BP, both rows ----
#pragma unroll
        for (int k = 0; k < CN_T; ++k) {
            const int m = tid + k * THREADS;
            const uint4 p0 = __ldg(&g_cnp[m * 3 + 0]);
            const uint4 p1 = __ldg(&g_cnp[m * 3 + 1]);
            const uint4 p2 = __ldg(&g_cnp[m * 3 + 2]);

            unsigned off[6] = { p0.x, p0.y, p0.z, p0.w, p1.x, p1.y };
            float    wgt[6] = { __uint_as_float(p1.z), __uint_as_float(p1.w),
                                __uint_as_float(p2.x), __uint_as_float(p2.y),
                                __uint_as_float(p2.z), __uint_as_float(p2.w) };

            float    ua[6], ub[6];
            unsigned sl = 0u, sh = 0u;   // per-row sign bitmasks (bit j)
            float Aa = 1.0f, Ba = 1.0f;  // prod (1-u), prod (1+u), row A
            float Ab = 1.0f, Bb = 1.0f;  // row B
#pragma unroll
            for (int j = 0; j < 6; ++j) {
                ull mm = *reinterpret_cast<const ull*>(
                             reinterpret_cast<const char*>(smem8) + off[j]);
                float xl, xh; upk2(mm, xl, xh);
                xl *= wgt[j];
                xh *= wgt[j];
                sl |= (__float_as_uint(xl) >> 31) << j;
                sh |= (__float_as_uint(xh) >> 31) << j;
                // u = e^{-|x|}  (so tanh(|x|/2) = (1-u)/(1+u))
                float va = ex2a(fabsf(xl) * -LOG2E_F);
                float vb = ex2a(fabsf(xh) * -LOG2E_F);
                va = fminf(va, UMAX_F);
                vb = fminf(vb, UMAX_F);
                ua[j] = va;  ub[j] = vb;
                Aa = fmaf(Aa, -va, Aa);  Ba = fmaf(Ba, va, Ba);
                Ab = fmaf(Ab, -vb, Ab);  Bb = fmaf(Bb, vb, Bb);
            }
            // w = prod tanh(|x_j|/2) = e^{-S}
            const float wa_ = Aa * rcpa(Ba);
            const float wb_ = Ab * rcpa(Bb);
            const float c1a = 1.0f + wa_, c2a = wa_ - 1.0f;
            const float c1b = 1.0f + wb_, c2b = wb_ - 1.0f;
            const unsigned pl = __popc(sl) & 1u;
            const unsigned ph = __popc(sh) & 1u;
#pragma unroll
            for (int j = 0; j < 6; ++j) {
                float va = ua[j], vb = ub[j];
                // z = w*(1+u)/(1-u);  mag = ln((1+z)/(1-z)) = 2*atanh(z)
                // num = (1-u) + w(1+u) = c1 + u*c2 ; den = (1-u) - w(1+u) = -c2 - u*c1
                float numa = fmaf(va,  c2a, c1a);
                float dena = fmaxf(fmaf(va, -c1a, -c2a), 1e-30f);
                float numb = fmaf(vb,  c2b, c1b);
                float denb = fmaxf(fmaf(vb, -c1b, -c2b), 1e-30f);
                float maga = fminf((lg2a(numa) - lg2a(dena)) * LN2_F, MAGMAX);
                float magb = fminf((lg2a(numb) - lg2a(denb)) * LN2_F, MAGMAX);
                unsigned rl = __float_as_uint(maga) | ((pl ^ ((sl >> j) & 1u)) << 31);
                unsigned rh = __float_as_uint(magb) | ((ph ^ ((sh >> j) & 1u)) << 31);
                *reinterpret_cast<ull*>(reinterpret_cast<char*>(smem8) + off[j]) =
                    pk2(__uint_as_float(rl), __uint_as_float(rh));
            }
        }
        __syncthreads();

        // ---- variable-node pass: coalesced SoA planes, llr from registers ----
        const bool last = (it == NITER - 1);
#pragma unroll
        for (int k = 0; k < VN_T; ++k) {
            const int v = tid + k * THREADS;
            ull m0 = P0[v];
            ull m1 = P1[v];
            ull m2 = P2[v];
            ull s  = add2(add2(m0, m1), m2);   // ascending edge order
            ull lt = add2(llr_r[k], s);
            if (last) {
                float a, b; upk2(lt, a, b);
                out[(size_t)rowA * NN + v]       = a;
                out[(size_t)(rowA + 1) * NN + v] = b;
            } else {
                P0[v] = fma2(m0, NEG1, lt);
                P1[v] = fma2(m1, NEG1, lt);
                P2[v] = fma2(m2, NEG1, lt);
            }
        }
        __syncthreads();
    }
}

// ---------------------------------------------------------------------------
// Launch
// ---------------------------------------------------------------------------
extern "C" void kernel_launch(void* const* d_in, const int* in_sizes, int n_in,
                              void* d_out, int out_size)
{
    const float* noise_r = (const float*)d_in[0];
    // d_in[1] = noise_i (unused by the reference)
    const float* weights = (const float*)d_in[2];
    // d_in[3] = vn_idx (structural: e/3)
    const int*   cn_idx  = (const int*)d_in[4];
    float* out = (float*)d_out;

    (void)in_sizes; (void)n_in; (void)out_size;

    cudaFuncSetAttribute(bp_kernel, cudaFuncAttributeMaxDynamicSharedMemorySize, SMEM_BYTES);

    prep_zero<<<(MM + 255) / 256, 256>>>();
    prep_fill<<<(EE + 255) / 256, 256>>>(cn_idx);
    prep_pack<<<(MM + 255) / 256, 256>>>(weights);

    bp_kernel<<<BB / 2, THREADS, SMEM_BYTES>>>(noise_r, out);
}